// round 5
// baseline (speedup 1.0000x reference)
#include <cuda_runtime.h>
#include <cuda_bf16.h>

// Fused Swin-style window attention, fp32 with packed f32x2 FMA,
// register-staged weight prefetch, double-buffered weight tiles
// (buffer 1 aliased over Ps), and 4m x 4n thread tiles in the weight
// GEMMs (64-column chunks, 48-row K quarters). One CTA per 8x8 window.
// B=4, H=W=256, C=192, WS=8, NH=6, HD=32.
//
// smem layout (floats):
//   Xs  [192][64]   X transposed (k-major); reused as attn-out^T for proj
//   Qs  [6][32][64] scaled Q, k(=d)-major
//   Ks  [6][32][64]
//   Vs  [6][64][32] natural (token-major)
//   Ps  [64][64]    softmax probs (attention) / weight buffer 1 (GEMMs)
//   Bt  [48][68]    weight buffer 0 (48 k-rows x 64 n-cols, stride 68)
//   Rs  [225*6]     relative-position-bias table

#define SM_X   0
#define SM_Q   12288
#define SM_K   24576
#define SM_V   36864
#define SM_P   49152
#define SM_B   53248
#define SM_R   56512
#define SM_FLOATS 57862
#define SMEM_BYTES (SM_FLOATS * 4)

#define WT_STRIDE 68   // 64 cols + 4 pad

typedef unsigned long long u64;

// packed f32x2 helpers (sm_100+ PTX; ptxas never emits FFMA2 on its own)
__device__ __forceinline__ u64 bc2(float v) {
    u64 r;
    asm("mov.b64 %0, {%1, %1};" : "=l"(r) : "r"(__float_as_uint(v)));
    return r;
}
__device__ __forceinline__ void fma2(u64& d, u64 a, u64 b) {
    asm("fma.rn.f32x2 %0, %1, %2, %0;" : "+l"(d) : "l"(a), "l"(b));
}
__device__ __forceinline__ u64 mul2(u64 a, u64 b) {
    u64 r;
    asm("mul.rn.f32x2 %0, %1, %2;" : "=l"(r) : "l"(a), "l"(b));
    return r;
}
__device__ __forceinline__ float2 unpk(u64 a) {
    unsigned lo, hi;
    asm("mov.b64 {%0, %1}, %2;" : "=r"(lo), "=r"(hi) : "l"(a));
    return make_float2(__uint_as_float(lo), __uint_as_float(hi));
}

__global__ __launch_bounds__(256, 1)
void win_attn_kernel(const float* __restrict__ x,
                     const float* __restrict__ qkv_w,
                     const float* __restrict__ proj_w,
                     const float* __restrict__ proj_b,
                     const float* __restrict__ rpb,
                     float* __restrict__ out)
{
    extern __shared__ float sm[];
    float* Xs  = sm + SM_X;
    float* Qs  = sm + SM_Q;
    float* Ks  = sm + SM_K;
    float* Vs  = sm + SM_V;
    float* Ps  = sm + SM_P;
    float* Rs  = sm + SM_R;
    float* wbuf[2];
    wbuf[0] = sm + SM_B;   // Bt0: 48*68 = 3264 floats
    wbuf[1] = sm + SM_P;   // Bt1 aliases Ps (disjoint lifetimes; 3264 <= 4096)

    const int tid = threadIdx.x;
    const int i = tid >> 4;      // m-group: rows 4i..4i+3
    const int j = tid & 15;      // n-group: cols 4j..4j+3 (within 64-col chunk)
    const int blk = blockIdx.x;
    const int b  = blk >> 10;
    const int wy = (blk >> 5) & 31;
    const int wx = blk & 31;
    // float offset of window origin pixel (b, wy*8, wx*8) in x/out
    const int base = ((b * 256 + wy * 8) * 256 + wx * 8) * 192;

    // ---- stage rpb table ----
    for (int t = tid; t < 1350; t += 256) Rs[t] = rpb[t];

    // ---- load X window transposed: Xs[k][m] ----
    #pragma unroll
    for (int p = 0; p < 12; p++) {
        int idx = p * 256 + tid;
        int m  = idx / 48;
        int c4 = idx % 48;
        float4 v = *(const float4*)(x + base + ((m >> 3) * 256 + (m & 7)) * 192 + c4 * 4);
        float* dst = Xs + c4 * 4 * 64 + m;
        dst[0]   = v.x;
        dst[64]  = v.y;
        dst[128] = v.z;
        dst[192] = v.w;
    }

    const u64 sc2 = bc2(0.17677669529663687f);  // 32^-0.5, packed

    // per-thread (n, k4) coords of the 3 weight float4s this thread stages:
    // tile = [48 k][64 n]; each thread loads 3 float4 along k.
    int wn[3], wk4[3];
    #pragma unroll
    for (int p = 0; p < 3; p++) {
        int idx = p * 256 + tid;             // 0..767
        wn[p]  = idx / 12;                   // 0..63  (output col within chunk)
        wk4[p] = idx % 12;                   // 0..11  (k/4 within 48-row quarter)
    }

    float4 wreg[3];
    // prologue: load + stage QKV weight tile 0 (chunk 0, quarter 0) into buf0
    #pragma unroll
    for (int p = 0; p < 3; p++)
        wreg[p] = *(const float4*)(qkv_w + wn[p] * 192 + wk4[p] * 4);
    #pragma unroll
    for (int p = 0; p < 3; p++) {
        float* dst = wbuf[0] + wk4[p] * 4 * WT_STRIDE + wn[p];
        dst[0]             = wreg[p].x;
        dst[WT_STRIDE]     = wreg[p].y;
        dst[2 * WT_STRIDE] = wreg[p].z;
        dst[3 * WT_STRIDE] = wreg[p].w;
    }
    __syncthreads();   // tile 0 staged (also orders Xs/Rs stores)

    // ---- GEMM1: QKV[64,576] = X[64,192] @ qkv_w^T ----
    // 9 chunks of 64 cols x 4 K-quarters of 48 = 36 tiles; epilogue at q==3.
    u64 acc2[2][4] = {};   // [m-pair][n]; m-pair 0 = rows i*4,i*4+1
    for (int t = 0; t < 36; t++) {
        const int cc   = t >> 2;
        const int q    = t & 3;
        const int koff = q * 48;
        // issue next tile's loads first (latency hides under compute)
        if (t + 1 < 36) {
            const int nn0   = ((t + 1) >> 2) * 64;
            const int nkoff = ((t + 1) & 3) * 48;
            #pragma unroll
            for (int p = 0; p < 3; p++)
                wreg[p] = *(const float4*)(qkv_w + (nn0 + wn[p]) * 192 + nkoff + wk4[p] * 4);
        }
        const float* Btc = wbuf[t & 1];
        const float* xk  = Xs + koff * 64;
        #pragma unroll 4
        for (int k = 0; k < 48; k++) {
            ulonglong2 a2 = *(const ulonglong2*)(xk + k * 64 + i * 4);
            float4 bb = *(const float4*)(Btc + k * WT_STRIDE + j * 4);
            u64 b0 = bc2(bb.x), b1 = bc2(bb.y), b2 = bc2(bb.z), b3 = bc2(bb.w);
            fma2(acc2[0][0], a2.x, b0); fma2(acc2[1][0], a2.y, b0);
            fma2(acc2[0][1], a2.x, b1); fma2(acc2[1][1], a2.y, b1);
            fma2(acc2[0][2], a2.x, b2); fma2(acc2[1][2], a2.y, b2);
            fma2(acc2[0][3], a2.x, b3); fma2(acc2[1][3], a2.y, b3);
        }
        // stage next tile into the other buffer
        if (t + 1 < 36) {
            float* bn = wbuf[(t + 1) & 1];
            #pragma unroll
            for (int p = 0; p < 3; p++) {
                float* dst = bn + wk4[p] * 4 * WT_STRIDE + wn[p];
                dst[0]             = wreg[p].x;
                dst[WT_STRIDE]     = wreg[p].y;
                dst[2 * WT_STRIDE] = wreg[p].z;
                dst[3 * WT_STRIDE] = wreg[p].w;
            }
        }
        if (q == 3) {
            // chunk cc complete: cols cc*64 .. cc*64+63 = (s, head pair)
            const int s  = cc / 3;             // 0=Q 1=K 2=V
            const int h  = (cc % 3) * 2 + (j >> 3);
            const int d0 = (j & 7) * 4;        // 4 d-cols within head
            if (s == 0) {
                float* q0 = Qs + h * 2048 + d0 * 64 + i * 4;
                #pragma unroll
                for (int c = 0; c < 4; c++) {
                    ulonglong2 cv;
                    cv.x = mul2(acc2[0][c], sc2);
                    cv.y = mul2(acc2[1][c], sc2);
                    *(ulonglong2*)(q0 + c * 64) = cv;
                }
            } else if (s == 1) {
                float* k0 = Ks + h * 2048 + d0 * 64 + i * 4;
                #pragma unroll
                for (int c = 0; c < 4; c++) {
                    ulonglong2 cv;
                    cv.x = acc2[0][c];
                    cv.y = acc2[1][c];
                    *(ulonglong2*)(k0 + c * 64) = cv;
                }
            } else {
                float* vh = Vs + h * 2048;
                float2 L[4], Hh[4];
                #pragma unroll
                for (int c = 0; c < 4; c++) { L[c] = unpk(acc2[0][c]); Hh[c] = unpk(acc2[1][c]); }
                *(float4*)(vh + (i * 4 + 0) * 32 + d0) = make_float4(L[0].x, L[1].x, L[2].x, L[3].x);
                *(float4*)(vh + (i * 4 + 1) * 32 + d0) = make_float4(L[0].y, L[1].y, L[2].y, L[3].y);
                *(float4*)(vh + (i * 4 + 2) * 32 + d0) = make_float4(Hh[0].x, Hh[1].x, Hh[2].x, Hh[3].x);
                *(float4*)(vh + (i * 4 + 3) * 32 + d0) = make_float4(Hh[0].y, Hh[1].y, Hh[2].y, Hh[3].y);
            }
            #pragma unroll
            for (int c = 0; c < 4; c++) { acc2[0][c] = 0ull; acc2[1][c] = 0ull; }
        }
        __syncthreads();   // tile t+1 staged; final barrier = Q/K/V complete
    }

    // prefetch proj weight tile 0 now; consumed after the whole attention
    // phase (~30K cycles later), so its latency is fully hidden.
    #pragma unroll
    for (int p = 0; p < 3; p++)
        wreg[p] = *(const float4*)(proj_w + wn[p] * 192 + wk4[p] * 4);

    // ---- precompute relative-position-bias offsets for this thread's S tile ----
    int ridx[4][4];
    #pragma unroll
    for (int di = 0; di < 4; di++) {
        int m = i * 4 + di, qr = m >> 3, qc = m & 7;
        #pragma unroll
        for (int dj = 0; dj < 4; dj++) {
            int n = j * 4 + dj, kr = n >> 3, kc = n & 7;
            ridx[di][dj] = ((qr - kr + 7) * 15 + (qc - kc + 7)) * 6;
        }
    }

    // ---- attention, one head at a time ----
    for (int h = 0; h < 6; h++) {
        const float* qh = Qs + h * 2048;
        const float* kh = Ks + h * 2048;
        u64 s2[4][2] = {};                       // [m][n-pair]
        #pragma unroll 4
        for (int d = 0; d < 32; d++) {
            float4 a      = *(const float4*)(qh + d * 64 + i * 4);
            ulonglong2 b2 = *(const ulonglong2*)(kh + d * 64 + j * 4);
            u64 a0 = bc2(a.x), a1 = bc2(a.y), a2b = bc2(a.z), a3 = bc2(a.w);
            fma2(s2[0][0], a0, b2.x);  fma2(s2[0][1], a0, b2.y);
            fma2(s2[1][0], a1, b2.x);  fma2(s2[1][1], a1, b2.y);
            fma2(s2[2][0], a2b, b2.x); fma2(s2[2][1], a2b, b2.y);
            fma2(s2[3][0], a3, b2.x);  fma2(s2[3][1], a3, b2.y);
        }
        // bias + softmax over the 64 keys; each row lives in one 16-lane group
        float p[4][4];
        #pragma unroll
        for (int di = 0; di < 4; di++) {
            float2 s01 = unpk(s2[di][0]), s23 = unpk(s2[di][1]);
            float sv0 = s01.x + Rs[ridx[di][0] + h];
            float sv1 = s01.y + Rs[ridx[di][1] + h];
            float sv2 = s23.x + Rs[ridx[di][2] + h];
            float sv3 = s23.y + Rs[ridx[di][3] + h];
            float mx = fmaxf(fmaxf(sv0, sv1), fmaxf(sv2, sv3));
            mx = fmaxf(mx, __shfl_xor_sync(0xffffffffu, mx, 8));
            mx = fmaxf(mx, __shfl_xor_sync(0xffffffffu, mx, 4));
            mx = fmaxf(mx, __shfl_xor_sync(0xffffffffu, mx, 2));
            mx = fmaxf(mx, __shfl_xor_sync(0xffffffffu, mx, 1));
            float e0 = __expf(sv0 - mx), e1 = __expf(sv1 - mx);
            float e2 = __expf(sv2 - mx), e3 = __expf(sv3 - mx);
            float sum = (e0 + e1) + (e2 + e3);
            sum += __shfl_xor_sync(0xffffffffu, sum, 8);
            sum += __shfl_xor_sync(0xffffffffu, sum, 4);
            sum += __shfl_xor_sync(0xffffffffu, sum, 2);
            sum += __shfl_xor_sync(0xffffffffu, sum, 1);
            float inv = __frcp_rn(sum);
            p[di][0] = e0 * inv; p[di][1] = e1 * inv;
            p[di][2] = e2 * inv; p[di][3] = e3 * inv;
        }
        __syncthreads();   // previous readers of Ps done (PV of h-1, or GEMM1 t=35)
        #pragma unroll
        for (int dj = 0; dj < 4; dj++)
            *(float4*)(Ps + (j * 4 + dj) * 64 + i * 4) =
                make_float4(p[0][dj], p[1][dj], p[2][dj], p[3][dj]);
        __syncthreads();   // Ps ready

        // PV: out_h[64,32] = P[64,64] @ V_h[64,32]
        const float* vh = Vs + h * 2048;
        u64 o2[2][2] = {};                       // [m-pair][n]
        #pragma unroll 4
        for (int kk = 0; kk < 64; kk++) {
            ulonglong2 a2 = *(const ulonglong2*)(Ps + kk * 64 + i * 4);
            float2 bv = *(const float2*)(vh + kk * 32 + j * 2);
            u64 b0 = bc2(bv.x), b1 = bc2(bv.y);
            fma2(o2[0][0], a2.x, b0); fma2(o2[0][1], a2.x, b1);
            fma2(o2[1][0], a2.y, b0); fma2(o2[1][1], a2.y, b1);
        }
        // store transposed attn output into Xs (now OsT[c][m]) for the proj GEMM
        float* ot = Xs + (h * 32 + j * 2) * 64 + i * 4;
        ulonglong2 c0, c1;
        c0.x = o2[0][0]; c0.y = o2[1][0];
        c1.x = o2[0][1]; c1.y = o2[1][1];
        *(ulonglong2*)ot        = c0;
        *(ulonglong2*)(ot + 64) = c1;
    }

    // ---- proj: out[64,192] = O[64,192] @ proj_w^T + proj_b ----
    // 3 chunks of 64 cols x 4 K-quarters = 12 tiles, double-buffered.
    #pragma unroll
    for (int p = 0; p < 3; p++) {
        float* dst = wbuf[0] + wk4[p] * 4 * WT_STRIDE + wn[p];
        dst[0]             = wreg[p].x;
        dst[WT_STRIDE]     = wreg[p].y;
        dst[2 * WT_STRIDE] = wreg[p].z;
        dst[3 * WT_STRIDE] = wreg[p].w;
    }
    __syncthreads();   // tile 0 staged; all PV Ps-reads + Xs writes done
    u64 pacc[2][4] = {};
    for (int t = 0; t < 12; t++) {
        const int cc   = t >> 2;
        const int q    = t & 3;
        const int koff = q * 48;
        if (t + 1 < 12) {
            const int nn0   = ((t + 1) >> 2) * 64;
            const int nkoff = ((t + 1) & 3) * 48;
            #pragma unroll
            for (int p = 0; p < 3; p++)
                wreg[p] = *(const float4*)(proj_w + (nn0 + wn[p]) * 192 + nkoff + wk4[p] * 4);
        }
        const float* Btc = wbuf[t & 1];
        const float* ok  = Xs + koff * 64;
        #pragma unroll 4
        for (int k = 0; k < 48; k++) {
            ulonglong2 a2 = *(const ulonglong2*)(ok + k * 64 + i * 4);
            float4 bb = *(const float4*)(Btc + k * WT_STRIDE + j * 4);
            u64 b0 = bc2(bb.x), b1 = bc2(bb.y), b2 = bc2(bb.z), b3 = bc2(bb.w);
            fma2(pacc[0][0], a2.x, b0); fma2(pacc[1][0], a2.y, b0);
            fma2(pacc[0][1], a2.x, b1); fma2(pacc[1][1], a2.y, b1);
            fma2(pacc[0][2], a2.x, b2); fma2(pacc[1][2], a2.y, b2);
            fma2(pacc[0][3], a2.x, b3); fma2(pacc[1][3], a2.y, b3);
        }
        if (t + 1 < 12) {
            float* bn = wbuf[(t + 1) & 1];
            #pragma unroll
            for (int p = 0; p < 3; p++) {
                float* dst = bn + wk4[p] * 4 * WT_STRIDE + wn[p];
                dst[0]             = wreg[p].x;
                dst[WT_STRIDE]     = wreg[p].y;
                dst[2 * WT_STRIDE] = wreg[p].z;
                dst[3 * WT_STRIDE] = wreg[p].w;
            }
        }
        if (q == 3) {
            const int n = cc * 64 + j * 4;
            float4 pb = *(const float4*)(proj_b + n);
            float2 L[4], Hh[4];
            #pragma unroll
            for (int c = 0; c < 4; c++) { L[c] = unpk(pacc[0][c]); Hh[c] = unpk(pacc[1][c]); }
            float4 r0 = make_float4(L[0].x + pb.x, L[1].x + pb.y, L[2].x + pb.z, L[3].x + pb.w);
            float4 r1 = make_float4(L[0].y + pb.x, L[1].y + pb.y, L[2].y + pb.z, L[3].y + pb.w);
            float4 r2 = make_float4(Hh[0].x + pb.x, Hh[1].x + pb.y, Hh[2].x + pb.z, Hh[3].x + pb.w);
            float4 r3 = make_float4(Hh[0].y + pb.x, Hh[1].y + pb.y, Hh[2].y + pb.z, Hh[3].y + pb.w);
            const int m0 = i * 4;
            float* po0 = out + base + (((m0 + 0) >> 3) * 256 + ((m0 + 0) & 7)) * 192 + n;
            float* po1 = out + base + (((m0 + 1) >> 3) * 256 + ((m0 + 1) & 7)) * 192 + n;
            float* po2 = out + base + (((m0 + 2) >> 3) * 256 + ((m0 + 2) & 7)) * 192 + n;
            float* po3 = out + base + (((m0 + 3) >> 3) * 256 + ((m0 + 3) & 7)) * 192 + n;
            *(float4*)po0 = r0;
            *(float4*)po1 = r1;
            *(float4*)po2 = r2;
            *(float4*)po3 = r3;
            #pragma unroll
            for (int c = 0; c < 4; c++) { pacc[0][c] = 0ull; pacc[1][c] = 0ull; }
        }
        if (t + 1 < 12) __syncthreads();   // tile t+1 staged
    }
}

extern "C" void kernel_launch(void* const* d_in, const int* in_sizes, int n_in,
                              void* d_out, int out_size) {
    (void)in_sizes; (void)n_in; (void)out_size;
    cudaFuncSetAttribute(win_attn_kernel,
                         cudaFuncAttributeMaxDynamicSharedMemorySize, SMEM_BYTES);
    win_attn_kernel<<<4096, 256, SMEM_BYTES>>>(
        (const float*)d_in[0],   // x
        (const float*)d_in[1],   // qkv_w
        (const float*)d_in[2],   // proj_w
        (const float*)d_in[3],   // proj_b
        (const float*)d_in[4],   // rpb_table
        (float*)d_out);
}